// round 1
// baseline (speedup 1.0000x reference)
#include <cuda_runtime.h>
#include <cuda_bf16.h>

#define N_NODES 50000
#define E_EDGES 800000
#define IN_C    16
#define HDIM    64
#define HH      32
#define EA_DIM  3
#define NLAYERS 3
#define FULL    0xffffffffu

// Scratch (device globals: no allocations allowed)
__device__ float g_h[N_NODES * HDIM];    // node features
__device__ float g_p[N_NODES * HH];      // per-node precomputed stage-1 (h @ W1a + b1)
__device__ float g_q[N_NODES * HH];      // aggregated relu(hidden) sums
__device__ float g_cnt[N_NODES];         // in-degree

// ---------------- degree count ----------------
__global__ void zero_cnt_kernel() {
    int i = blockIdx.x * blockDim.x + threadIdx.x;
    if (i < N_NODES) g_cnt[i] = 0.0f;
}

__global__ void count_kernel(const int* __restrict__ ei) {
    int e = blockIdx.x * blockDim.x + threadIdx.x;
    if (e < E_EDGES) atomicAdd(&g_cnt[ei[E_EDGES + e]], 1.0f);
}

// ---------------- encoder: h = relu(LN(x @ enc_w + enc_b)) ----------------
__global__ __launch_bounds__(256) void encoder_kernel(
    const float* __restrict__ x, const float* __restrict__ w,
    const float* __restrict__ b, const float* __restrict__ g,
    const float* __restrict__ beta)
{
    int n    = (blockIdx.x * blockDim.x + threadIdx.x) >> 5;
    int lane = threadIdx.x & 31;
    if (n >= N_NODES) return;

    float xv = (lane < IN_C) ? x[n * IN_C + lane] : 0.0f;
    float a0 = b[lane], a1 = b[lane + 32];
#pragma unroll
    for (int k = 0; k < IN_C; k++) {
        float xk = __shfl_sync(FULL, xv, k);
        a0 = fmaf(xk, __ldg(&w[k * HDIM + lane]),      a0);
        a1 = fmaf(xk, __ldg(&w[k * HDIM + 32 + lane]), a1);
    }
    // LayerNorm over 64 values (each lane holds 2)
    float s1 = a0 + a1, s2 = a0 * a0 + a1 * a1;
#pragma unroll
    for (int o = 16; o; o >>= 1) {
        s1 += __shfl_xor_sync(FULL, s1, o);
        s2 += __shfl_xor_sync(FULL, s2, o);
    }
    float mu  = s1 * (1.0f / 64.0f);
    float var = s2 * (1.0f / 64.0f) - mu * mu;
    float rs  = rsqrtf(var + 1e-5f);
    float h0  = fmaxf(fmaf((a0 - mu) * rs, __ldg(&g[lane]),      __ldg(&beta[lane])),      0.0f);
    float h1  = fmaxf(fmaf((a1 - mu) * rs, __ldg(&g[lane + 32]), __ldg(&beta[lane + 32])), 0.0f);
    g_h[n * HDIM + lane]      = h0;
    g_h[n * HDIM + 32 + lane] = h1;
}

// ---------------- per-node stage-1 precompute: p = h @ W1[:64] + b1; also zero q ----------------
__global__ __launch_bounds__(256) void node_p_kernel(
    const float* __restrict__ w1, const float* __restrict__ b1)
{
    int n    = (blockIdx.x * blockDim.x + threadIdx.x) >> 5;
    int lane = threadIdx.x & 31;
    if (n >= N_NODES) return;

    g_q[n * HH + lane] = 0.0f;

    float h0 = g_h[n * HDIM + lane];
    float h1 = g_h[n * HDIM + 32 + lane];
    float acc = __ldg(&b1[lane]);
#pragma unroll
    for (int k = 0; k < 32; k++) {
        float hk = __shfl_sync(FULL, h0, k);
        acc = fmaf(hk, __ldg(&w1[k * HH + lane]), acc);
    }
#pragma unroll
    for (int k = 0; k < 32; k++) {
        float hk = __shfl_sync(FULL, h1, k);
        acc = fmaf(hk, __ldg(&w1[(32 + k) * HH + lane]), acc);
    }
    g_p[n * HH + lane] = acc;
}

// ---------------- edge kernel: q[dst] += relu(p[src] + ea @ W1[64:67]) ----------------
__global__ __launch_bounds__(256) void edge_kernel(
    const int* __restrict__ ei, const float* __restrict__ ea,
    const float* __restrict__ w1)
{
    int e    = (blockIdx.x * blockDim.x + threadIdx.x) >> 5;
    int lane = threadIdx.x & 31;
    if (e >= E_EDGES) return;

    int src = __ldg(&ei[e]);
    int dst = __ldg(&ei[E_EDGES + e]);
    float e0 = __ldg(&ea[e * 3 + 0]);
    float e1 = __ldg(&ea[e * 3 + 1]);
    float e2 = __ldg(&ea[e * 3 + 2]);

    float v = g_p[src * HH + lane];
    v = fmaf(e0, __ldg(&w1[64 * HH + lane]), v);
    v = fmaf(e1, __ldg(&w1[65 * HH + lane]), v);
    v = fmaf(e2, __ldg(&w1[66 * HH + lane]), v);
    v = fmaxf(v, 0.0f);
    atomicAdd(&g_q[dst * HH + lane], v);
}

// ---------------- per-node stage-2 + mean + residual + LN ----------------
__global__ __launch_bounds__(256) void node_agg_ln_kernel(
    const float* __restrict__ w2, const float* __restrict__ b2,
    const float* __restrict__ g,  const float* __restrict__ beta)
{
    int n    = (blockIdx.x * blockDim.x + threadIdx.x) >> 5;
    int lane = threadIdx.x & 31;
    if (n >= N_NODES) return;

    float qv = g_q[n * HH + lane];
    float o0 = 0.0f, o1 = 0.0f;
#pragma unroll
    for (int j = 0; j < 32; j++) {
        float qj = __shfl_sync(FULL, qv, j);
        o0 = fmaf(qj, __ldg(&w2[j * HDIM + lane]),      o0);
        o1 = fmaf(qj, __ldg(&w2[j * HDIM + 32 + lane]), o1);
    }
    float c   = g_cnt[n];
    float inv = (c > 0.0f) ? (1.0f / c) : 0.0f;
    float has = (c > 0.0f) ? 1.0f : 0.0f;
    // agg = (q @ W2) * inv + b2 * (cnt>0)   [== (segsum(m)) * inv_cnt]
    float a0 = g_h[n * HDIM + lane]      + o0 * inv + has * __ldg(&b2[lane]);
    float a1 = g_h[n * HDIM + 32 + lane] + o1 * inv + has * __ldg(&b2[32 + lane]);

    float s1 = a0 + a1, s2 = a0 * a0 + a1 * a1;
#pragma unroll
    for (int o = 16; o; o >>= 1) {
        s1 += __shfl_xor_sync(FULL, s1, o);
        s2 += __shfl_xor_sync(FULL, s2, o);
    }
    float mu  = s1 * (1.0f / 64.0f);
    float var = s2 * (1.0f / 64.0f) - mu * mu;
    float rs  = rsqrtf(var + 1e-5f);
    g_h[n * HDIM + lane]      = fmaf((a0 - mu) * rs, __ldg(&g[lane]),      __ldg(&beta[lane]));
    g_h[n * HDIM + 32 + lane] = fmaf((a1 - mu) * rs, __ldg(&g[lane + 32]), __ldg(&beta[lane + 32]));
}

// ---------------- heads ----------------
__global__ __launch_bounds__(256) void heads_kernel(
    const float* __restrict__ dw1, const float* __restrict__ db1,
    const float* __restrict__ dw2, const float* __restrict__ db2,
    const float* __restrict__ vw1, const float* __restrict__ vb1,
    const float* __restrict__ vw2, const float* __restrict__ vb2,
    float* __restrict__ out)
{
    int n    = (blockIdx.x * blockDim.x + threadIdx.x) >> 5;
    int lane = threadIdx.x & 31;
    if (n >= N_NODES) return;

    float h0 = g_h[n * HDIM + lane];
    float h1 = g_h[n * HDIM + 32 + lane];

    float da = __ldg(&db1[lane]);
    float va = __ldg(&vb1[lane]);
#pragma unroll
    for (int k = 0; k < 32; k++) {
        float hk = __shfl_sync(FULL, h0, k);
        da = fmaf(hk, __ldg(&dw1[k * HH + lane]), da);
        va = fmaf(hk, __ldg(&vw1[k * HH + lane]), va);
    }
#pragma unroll
    for (int k = 0; k < 32; k++) {
        float hk = __shfl_sync(FULL, h1, k);
        da = fmaf(hk, __ldg(&dw1[(32 + k) * HH + lane]), da);
        va = fmaf(hk, __ldg(&vw1[(32 + k) * HH + lane]), va);
    }
    da = fmaxf(da, 0.0f);
    va = fmaxf(va, 0.0f);

    float dsum = da * __ldg(&dw2[lane]);          // depth_w2: [32,1]
    float v0   = va * __ldg(&vw2[lane * 2 + 0]);  // vel_w2:   [32,2]
    float v1   = va * __ldg(&vw2[lane * 2 + 1]);
#pragma unroll
    for (int o = 16; o; o >>= 1) {
        dsum += __shfl_xor_sync(FULL, dsum, o);
        v0   += __shfl_xor_sync(FULL, v0, o);
        v1   += __shfl_xor_sync(FULL, v1, o);
    }
    if (lane == 0) {
        out[n]                       = dsum + __ldg(&db2[0]);
        out[N_NODES + n * 2 + 0]     = v0   + __ldg(&vb2[0]);
        out[N_NODES + n * 2 + 1]     = v1   + __ldg(&vb2[1]);
    }
}

// ---------------- launch ----------------
extern "C" void kernel_launch(void* const* d_in, const int* in_sizes, int n_in,
                              void* d_out, int out_size)
{
    const float* x       = (const float*)d_in[0];
    const int*   ei      = (const int*)  d_in[1];
    const float* ea      = (const float*)d_in[2];
    const float* enc_w   = (const float*)d_in[3];
    const float* enc_b   = (const float*)d_in[4];
    const float* enc_g   = (const float*)d_in[5];
    const float* enc_bt  = (const float*)d_in[6];
    const float* mlp_w1  = (const float*)d_in[7];   // [L, 67, 32]
    const float* mlp_b1  = (const float*)d_in[8];   // [L, 32]
    const float* mlp_w2  = (const float*)d_in[9];   // [L, 32, 64]
    const float* mlp_b2  = (const float*)d_in[10];  // [L, 64]
    const float* ln_g    = (const float*)d_in[11];  // [L, 64]
    const float* ln_b    = (const float*)d_in[12];  // [L, 64]
    const float* dw1     = (const float*)d_in[13];
    const float* db1     = (const float*)d_in[14];
    const float* dw2     = (const float*)d_in[15];
    const float* db2     = (const float*)d_in[16];
    const float* vw1     = (const float*)d_in[17];
    const float* vb1     = (const float*)d_in[18];
    const float* vw2     = (const float*)d_in[19];
    const float* vb2     = (const float*)d_in[20];
    float* out = (float*)d_out;

    const int TB = 256;
    const int node_warp_grid = (N_NODES + 7) / 8;   // 8 warps/block, warp per node
    const int edge_warp_grid = (E_EDGES + 7) / 8;

    zero_cnt_kernel<<<(N_NODES + TB - 1) / TB, TB>>>();
    count_kernel<<<(E_EDGES + TB - 1) / TB, TB>>>(ei);
    encoder_kernel<<<node_warp_grid, TB>>>(x, enc_w, enc_b, enc_g, enc_bt);

    for (int i = 0; i < NLAYERS; i++) {
        const float* w1 = mlp_w1 + (size_t)i * (HDIM + EA_DIM) * HH;
        const float* b1 = mlp_b1 + (size_t)i * HH;
        const float* w2 = mlp_w2 + (size_t)i * HH * HDIM;
        const float* b2 = mlp_b2 + (size_t)i * HDIM;
        const float* lg = ln_g   + (size_t)i * HDIM;
        const float* lb = ln_b   + (size_t)i * HDIM;

        node_p_kernel<<<node_warp_grid, TB>>>(w1, b1);
        edge_kernel<<<edge_warp_grid, TB>>>(ei, ea, w1);
        node_agg_ln_kernel<<<node_warp_grid, TB>>>(w2, b2, lg, lb);
    }

    heads_kernel<<<node_warp_grid, TB>>>(dw1, db1, dw2, db2, vw1, vb1, vw2, vb2, out);
}

// round 2
// speedup vs baseline: 1.8090x; 1.8090x over previous
#include <cuda_runtime.h>
#include <cuda_bf16.h>

#define N_NODES 50000
#define E_EDGES 800000
#define IN_C    16
#define HDIM    64
#define HH      32
#define EA_DIM  3
#define NLAYERS 3
#define FULL    0xffffffffu

// Scratch (device globals; float4 to guarantee 16B alignment)
__device__ float  g_h[N_NODES * HDIM];     // node features
__device__ float4 g_p4[N_NODES * 8];       // per-node stage-1 (h @ W1a + b1), 32 floats/node
__device__ float4 g_q4[N_NODES * 8];       // aggregated relu(hidden) sums, 32 floats/node
__device__ float  g_cnt[N_NODES];          // in-degree

__device__ __forceinline__ void red_add_v4(float* ptr, float4 v) {
    asm volatile("red.global.add.v4.f32 [%0], {%1,%2,%3,%4};"
                 :: "l"(ptr), "f"(v.x), "f"(v.y), "f"(v.z), "f"(v.w) : "memory");
}

// ---------------- degree count ----------------
__global__ void count_kernel(const int* __restrict__ ei) {
    int e = blockIdx.x * blockDim.x + threadIdx.x;
    if (e < E_EDGES) atomicAdd(&g_cnt[ei[E_EDGES + e]], 1.0f);
}

// ---------------- encoder: h = relu(LN(x@enc_w+enc_b)); fused p0 = h@W1a+b1; zero q,cnt ----
__global__ __launch_bounds__(256) void encoder_kernel(
    const float* __restrict__ x,  const float* __restrict__ w,
    const float* __restrict__ b,  const float* __restrict__ g,
    const float* __restrict__ beta,
    const float* __restrict__ w1, const float* __restrict__ b1)
{
    int warp = (blockIdx.x * blockDim.x + threadIdx.x) >> 5;
    int lane = threadIdx.x & 31;
    int n0   = warp * 4;
    if (n0 >= N_NODES) return;   // N divisible by 4, no partial groups

    float* g_p = (float*)g_p4;
    float* g_q = (float*)g_q4;

    float xv[4], a0[4], a1[4];
#pragma unroll
    for (int i = 0; i < 4; i++) {
        xv[i] = (lane < IN_C) ? x[(n0 + i) * IN_C + lane] : 0.0f;
        a0[i] = __ldg(&b[lane]);
        a1[i] = __ldg(&b[lane + 32]);
    }
#pragma unroll
    for (int k = 0; k < IN_C; k++) {
        float w0 = __ldg(&w[k * HDIM + lane]);
        float w1v = __ldg(&w[k * HDIM + 32 + lane]);
#pragma unroll
        for (int i = 0; i < 4; i++) {
            float xk = __shfl_sync(FULL, xv[i], k);
            a0[i] = fmaf(xk, w0, a0[i]);
            a1[i] = fmaf(xk, w1v, a1[i]);
        }
    }
    float gl = __ldg(&g[lane]), gh = __ldg(&g[lane + 32]);
    float bl = __ldg(&beta[lane]), bh = __ldg(&beta[lane + 32]);
    float h0[4], h1[4];
#pragma unroll
    for (int i = 0; i < 4; i++) {
        float s1 = a0[i] + a1[i], s2 = a0[i] * a0[i] + a1[i] * a1[i];
#pragma unroll
        for (int o = 16; o; o >>= 1) {
            s1 += __shfl_xor_sync(FULL, s1, o);
            s2 += __shfl_xor_sync(FULL, s2, o);
        }
        float mu  = s1 * (1.0f / 64.0f);
        float var = s2 * (1.0f / 64.0f) - mu * mu;
        float rs  = rsqrtf(var + 1e-5f);
        h0[i] = fmaxf(fmaf((a0[i] - mu) * rs, gl, bl), 0.0f);
        h1[i] = fmaxf(fmaf((a1[i] - mu) * rs, gh, bh), 0.0f);
        g_h[(n0 + i) * HDIM + lane]      = h0[i];
        g_h[(n0 + i) * HDIM + 32 + lane] = h1[i];
    }
    // fused p = h @ W1[:64] + b1
    float acc[4];
#pragma unroll
    for (int i = 0; i < 4; i++) acc[i] = __ldg(&b1[lane]);
#pragma unroll
    for (int k = 0; k < 32; k++) {
        float wk = __ldg(&w1[k * HH + lane]);
#pragma unroll
        for (int i = 0; i < 4; i++)
            acc[i] = fmaf(__shfl_sync(FULL, h0[i], k), wk, acc[i]);
    }
#pragma unroll
    for (int k = 0; k < 32; k++) {
        float wk = __ldg(&w1[(32 + k) * HH + lane]);
#pragma unroll
        for (int i = 0; i < 4; i++)
            acc[i] = fmaf(__shfl_sync(FULL, h1[i], k), wk, acc[i]);
    }
#pragma unroll
    for (int i = 0; i < 4; i++) {
        g_p[(n0 + i) * HH + lane] = acc[i];
        g_q[(n0 + i) * HH + lane] = 0.0f;
    }
    if (lane < 4) g_cnt[n0 + lane] = 0.0f;
}

// ---------------- edge kernel: q[dst] += relu(p[src] + ea @ W1[64:67]); 8 thr/edge ----------
__global__ __launch_bounds__(256) void edge_kernel(
    const int* __restrict__ ei, const float* __restrict__ ea,
    const float* __restrict__ w1)
{
    int idx  = blockIdx.x * blockDim.x + threadIdx.x;
    int e    = idx >> 3;
    int quad = idx & 7;
    if (e >= E_EDGES) return;

    int src = __ldg(&ei[e]);
    int dst = __ldg(&ei[E_EDGES + e]);
    float e0 = __ldg(&ea[e * 3 + 0]);
    float e1 = __ldg(&ea[e * 3 + 1]);
    float e2 = __ldg(&ea[e * 3 + 2]);

    float4 p = __ldg(&g_p4[src * 8 + quad]);
    const float4* W = (const float4*)(w1 + 64 * HH);
    float4 wa = __ldg(&W[quad]);
    float4 wb = __ldg(&W[8 + quad]);
    float4 wc = __ldg(&W[16 + quad]);

    float4 v;
    v.x = fmaxf(fmaf(e2, wc.x, fmaf(e1, wb.x, fmaf(e0, wa.x, p.x))), 0.0f);
    v.y = fmaxf(fmaf(e2, wc.y, fmaf(e1, wb.y, fmaf(e0, wa.y, p.y))), 0.0f);
    v.z = fmaxf(fmaf(e2, wc.z, fmaf(e1, wb.z, fmaf(e0, wa.z, p.z))), 0.0f);
    v.w = fmaxf(fmaf(e2, wc.w, fmaf(e1, wb.w, fmaf(e0, wa.w, p.w))), 0.0f);

    red_add_v4((float*)&g_q4[dst * 8 + quad], v);
}

// ---- stage-2 + mean + residual + LN; fused: zero q, and p for next layer if w1n ----
__global__ __launch_bounds__(256) void node_agg_ln_kernel(
    const float* __restrict__ w2,  const float* __restrict__ b2,
    const float* __restrict__ g,   const float* __restrict__ beta,
    const float* __restrict__ w1n, const float* __restrict__ b1n)
{
    int warp = (blockIdx.x * blockDim.x + threadIdx.x) >> 5;
    int lane = threadIdx.x & 31;
    int n0   = warp * 4;
    if (n0 >= N_NODES) return;

    float* g_p = (float*)g_p4;
    float* g_q = (float*)g_q4;

    float qv[4];
#pragma unroll
    for (int i = 0; i < 4; i++) {
        qv[i] = g_q[(n0 + i) * HH + lane];
        g_q[(n0 + i) * HH + lane] = 0.0f;   // ready for next layer
    }
    float o0[4] = {0, 0, 0, 0}, o1[4] = {0, 0, 0, 0};
#pragma unroll
    for (int j = 0; j < 32; j++) {
        float w0 = __ldg(&w2[j * HDIM + lane]);
        float w1v = __ldg(&w2[j * HDIM + 32 + lane]);
#pragma unroll
        for (int i = 0; i < 4; i++) {
            float qj = __shfl_sync(FULL, qv[i], j);
            o0[i] = fmaf(qj, w0, o0[i]);
            o1[i] = fmaf(qj, w1v, o1[i]);
        }
    }
    float gl = __ldg(&g[lane]), gh = __ldg(&g[lane + 32]);
    float bl = __ldg(&beta[lane]), bh = __ldg(&beta[lane + 32]);
    float b2l = __ldg(&b2[lane]), b2h = __ldg(&b2[32 + lane]);

    float h0[4], h1[4];
#pragma unroll
    for (int i = 0; i < 4; i++) {
        float c   = g_cnt[n0 + i];
        float inv = (c > 0.0f) ? (1.0f / c) : 0.0f;
        float has = (c > 0.0f) ? 1.0f : 0.0f;
        float a0 = g_h[(n0 + i) * HDIM + lane]      + o0[i] * inv + has * b2l;
        float a1 = g_h[(n0 + i) * HDIM + 32 + lane] + o1[i] * inv + has * b2h;
        float s1 = a0 + a1, s2 = a0 * a0 + a1 * a1;
#pragma unroll
        for (int o = 16; o; o >>= 1) {
            s1 += __shfl_xor_sync(FULL, s1, o);
            s2 += __shfl_xor_sync(FULL, s2, o);
        }
        float mu  = s1 * (1.0f / 64.0f);
        float var = s2 * (1.0f / 64.0f) - mu * mu;
        float rs  = rsqrtf(var + 1e-5f);
        h0[i] = fmaf((a0 - mu) * rs, gl, bl);
        h1[i] = fmaf((a1 - mu) * rs, gh, bh);
        g_h[(n0 + i) * HDIM + lane]      = h0[i];
        g_h[(n0 + i) * HDIM + 32 + lane] = h1[i];
    }

    if (w1n != nullptr) {   // fused p for next layer
        float acc[4];
#pragma unroll
        for (int i = 0; i < 4; i++) acc[i] = __ldg(&b1n[lane]);
#pragma unroll
        for (int k = 0; k < 32; k++) {
            float wk = __ldg(&w1n[k * HH + lane]);
#pragma unroll
            for (int i = 0; i < 4; i++)
                acc[i] = fmaf(__shfl_sync(FULL, h0[i], k), wk, acc[i]);
        }
#pragma unroll
        for (int k = 0; k < 32; k++) {
            float wk = __ldg(&w1n[(32 + k) * HH + lane]);
#pragma unroll
            for (int i = 0; i < 4; i++)
                acc[i] = fmaf(__shfl_sync(FULL, h1[i], k), wk, acc[i]);
        }
#pragma unroll
        for (int i = 0; i < 4; i++)
            g_p[(n0 + i) * HH + lane] = acc[i];
    }
}

// ---------------- heads ----------------
__global__ __launch_bounds__(256) void heads_kernel(
    const float* __restrict__ dw1, const float* __restrict__ db1,
    const float* __restrict__ dw2, const float* __restrict__ db2,
    const float* __restrict__ vw1, const float* __restrict__ vb1,
    const float* __restrict__ vw2, const float* __restrict__ vb2,
    float* __restrict__ out)
{
    int warp = (blockIdx.x * blockDim.x + threadIdx.x) >> 5;
    int lane = threadIdx.x & 31;
    int n0   = warp * 4;
    if (n0 >= N_NODES) return;

    float h0[4], h1[4], da[4], va[4];
#pragma unroll
    for (int i = 0; i < 4; i++) {
        h0[i] = g_h[(n0 + i) * HDIM + lane];
        h1[i] = g_h[(n0 + i) * HDIM + 32 + lane];
        da[i] = __ldg(&db1[lane]);
        va[i] = __ldg(&vb1[lane]);
    }
#pragma unroll
    for (int k = 0; k < 32; k++) {
        float dwk = __ldg(&dw1[k * HH + lane]);
        float vwk = __ldg(&vw1[k * HH + lane]);
#pragma unroll
        for (int i = 0; i < 4; i++) {
            float hk = __shfl_sync(FULL, h0[i], k);
            da[i] = fmaf(hk, dwk, da[i]);
            va[i] = fmaf(hk, vwk, va[i]);
        }
    }
#pragma unroll
    for (int k = 0; k < 32; k++) {
        float dwk = __ldg(&dw1[(32 + k) * HH + lane]);
        float vwk = __ldg(&vw1[(32 + k) * HH + lane]);
#pragma unroll
        for (int i = 0; i < 4; i++) {
            float hk = __shfl_sync(FULL, h1[i], k);
            da[i] = fmaf(hk, dwk, da[i]);
            va[i] = fmaf(hk, vwk, va[i]);
        }
    }
    float w2d = __ldg(&dw2[lane]);
    float w2v0 = __ldg(&vw2[lane * 2 + 0]);
    float w2v1 = __ldg(&vw2[lane * 2 + 1]);
#pragma unroll
    for (int i = 0; i < 4; i++) {
        float d  = fmaxf(da[i], 0.0f) * w2d;
        float v0 = fmaxf(va[i], 0.0f) * w2v0;
        float v1 = fmaxf(va[i], 0.0f) * w2v1;
#pragma unroll
        for (int o = 16; o; o >>= 1) {
            d  += __shfl_xor_sync(FULL, d, o);
            v0 += __shfl_xor_sync(FULL, v0, o);
            v1 += __shfl_xor_sync(FULL, v1, o);
        }
        if (lane == 0) {
            out[n0 + i]                     = d  + __ldg(&db2[0]);
            out[N_NODES + (n0 + i) * 2 + 0] = v0 + __ldg(&vb2[0]);
            out[N_NODES + (n0 + i) * 2 + 1] = v1 + __ldg(&vb2[1]);
        }
    }
}

// ---------------- launch ----------------
extern "C" void kernel_launch(void* const* d_in, const int* in_sizes, int n_in,
                              void* d_out, int out_size)
{
    const float* x       = (const float*)d_in[0];
    const int*   ei      = (const int*)  d_in[1];
    const float* ea      = (const float*)d_in[2];
    const float* enc_w   = (const float*)d_in[3];
    const float* enc_b   = (const float*)d_in[4];
    const float* enc_g   = (const float*)d_in[5];
    const float* enc_bt  = (const float*)d_in[6];
    const float* mlp_w1  = (const float*)d_in[7];   // [L, 67, 32]
    const float* mlp_b1  = (const float*)d_in[8];   // [L, 32]
    const float* mlp_w2  = (const float*)d_in[9];   // [L, 32, 64]
    const float* mlp_b2  = (const float*)d_in[10];  // [L, 64]
    const float* ln_g    = (const float*)d_in[11];  // [L, 64]
    const float* ln_b    = (const float*)d_in[12];  // [L, 64]
    const float* dw1     = (const float*)d_in[13];
    const float* db1     = (const float*)d_in[14];
    const float* dw2     = (const float*)d_in[15];
    const float* db2     = (const float*)d_in[16];
    const float* vw1     = (const float*)d_in[17];
    const float* vb1     = (const float*)d_in[18];
    const float* vw2     = (const float*)d_in[19];
    const float* vb2     = (const float*)d_in[20];
    float* out = (float*)d_out;

    const int TB = 256;
    const int node_grid = (N_NODES / 4 * 32 + TB - 1) / TB;     // 4 nodes/warp
    const int edge_grid = (E_EDGES * 8 + TB - 1) / TB;          // 8 threads/edge

    // encoder also zeroes q and cnt, and computes p for layer 0
    encoder_kernel<<<node_grid, TB>>>(x, enc_w, enc_b, enc_g, enc_bt,
                                      mlp_w1, mlp_b1);
    count_kernel<<<(E_EDGES + TB - 1) / TB, TB>>>(ei);

    for (int i = 0; i < NLAYERS; i++) {
        const float* w1 = mlp_w1 + (size_t)i * (HDIM + EA_DIM) * HH;
        const float* w2 = mlp_w2 + (size_t)i * HH * HDIM;
        const float* b2 = mlp_b2 + (size_t)i * HDIM;
        const float* lg = ln_g   + (size_t)i * HDIM;
        const float* lb = ln_b   + (size_t)i * HDIM;
        const float* w1n = (i + 1 < NLAYERS) ? mlp_w1 + (size_t)(i + 1) * (HDIM + EA_DIM) * HH : nullptr;
        const float* b1n = (i + 1 < NLAYERS) ? mlp_b1 + (size_t)(i + 1) * HH : nullptr;

        edge_kernel<<<edge_grid, TB>>>(ei, ea, w1);
        node_agg_ln_kernel<<<node_grid, TB>>>(w2, b2, lg, lb, w1n, b1n);
    }

    heads_kernel<<<node_grid, TB>>>(dw1, db1, dw2, db2, vw1, vb1, vw2, vb2, out);
}